// round 8
// baseline (speedup 1.0000x reference)
#include <cuda_runtime.h>

// inputs (128, 64, 64, 32) fp32 => B=128, N=64 rows/batch, D=2048.
// loss = mean_b( || sum_n att[b,n,:] ||^2 - sum_n <att_n,att_n> ),
// att = x / max(||x||,1e-12) row-wise.
//
// Grid 256 = 2 blocks per batch (half h=0/1), 1024 threads each -> 2 CTAs/SM,
// 100% occupancy, all co-resident (spin-sync safe).
//  Phase A: half h computes norms of rows [32h,32h+32) -> g_inv (global)
//  Pair sync: monotonic per-batch counter (no reset; replays serialized)
//  Phase B: half h sums its 256 f4-columns; 4 threads/column x 16 rows
// Finisher (monotonic election) combines 256 double partials.

#define BB    128
#define NN    64
#define DD    2048
#define NF4   (DD / 4)     // 512 float4 columns
#define NT    1024
#define HB    2            // blocks per batch
#define GRID  (BB * HB)    // 256
#define CPB   (NF4 / HB)   // 256 f4-columns per block
#define EPS   1e-12

__device__ float        g_inv[BB * NN];
__device__ double       g_part[GRID];
__device__ unsigned int g_arrive[BB];   // monotonic, never reset
__device__ unsigned int g_done;         // monotonic, never reset

__global__ __launch_bounds__(NT) void fused_loss(const float* __restrict__ x,
                                                 float* __restrict__ out) {
    const int bid  = blockIdx.x;
    const int b    = bid >> 1;          // batch
    const int h    = bid & 1;           // half
    const int t    = threadIdx.x;
    const int warp = t >> 5;
    const int lane = t & 31;
    const float4* base4 = reinterpret_cast<const float4*>(x + (size_t)b * NN * DD);

    __shared__ float  s_inv[NN];
    __shared__ float4 s_part[(4 - 1) * CPB];   // quarters 1..3 partial col sums
    __shared__ float  w1[NT / 32], w2[NT / 32];

    // ---------------- Phase A: norms of rows [32h, 32h+32), 1 row/warp ------
    const int row = h * 32 + warp;
    float my_diag = 0.f;
    {
        const float4* p = base4 + row * NF4 + lane;
        float s0 = 0.f, s1 = 0.f, s2 = 0.f, s3 = 0.f;
        #pragma unroll
        for (int i = 0; i < 16; i += 4) {
            const float4 a = p[(i + 0) * 32];
            const float4 c = p[(i + 1) * 32];
            const float4 d = p[(i + 2) * 32];
            const float4 e = p[(i + 3) * 32];
            s0 += a.x*a.x + a.y*a.y + a.z*a.z + a.w*a.w;
            s1 += c.x*c.x + c.y*c.y + c.z*c.z + c.w*c.w;
            s2 += d.x*d.x + d.y*d.y + d.z*d.z + d.w*d.w;
            s3 += e.x*e.x + e.y*e.y + e.z*e.z + e.w*e.w;
        }
        float ss = (s0 + s1) + (s2 + s3);
        #pragma unroll
        for (int o = 16; o; o >>= 1) ss += __shfl_xor_sync(0xffffffffu, ss, o);
        if (lane == 0) {
            double sd  = (double)ss;
            double nrm = sqrt(sd);
            if (nrm < EPS) nrm = EPS;
            g_inv[b * NN + row] = (float)(1.0 / nrm);
            my_diag = (float)(sd / (nrm * nrm));     // kept in register
        }
    }
    __syncthreads();                    // all g_inv writes of this block issued

    // ---------------- Pair sync: monotonic counter --------------------------
    if (t == 0) {
        __threadfence();
        unsigned int old    = atomicAdd(&g_arrive[b], 1u);
        unsigned int target = ((old >> 1) + 1u) * 2u;
        while (atomicAdd(&g_arrive[b], 0u) < target) __nanosleep(32);
    }
    __syncthreads();
    __threadfence();                    // acquire peer's g_inv writes

    if (t < NN) s_inv[t] = g_inv[b * NN + t];
    __syncthreads();

    // ---------------- Phase B: this block's 256 f4-columns ------------------
    // 4 threads per column: quarter q = t>>8 sums rows [16q, 16q+16).
    const int col = h * CPB + (t & (CPB - 1));
    const int q   = t >> 8;
    const float4* p  = base4 + (q * 16) * NF4 + col;
    const float*  wv = s_inv + q * 16;

    float4 s = make_float4(0.f, 0.f, 0.f, 0.f);
    #pragma unroll 8
    for (int n = 0; n < 16; n++) {
        const float  w = wv[n];
        const float4 a = p[n * NF4];
        s.x = fmaf(w, a.x, s.x); s.y = fmaf(w, a.y, s.y);
        s.z = fmaf(w, a.z, s.z); s.w = fmaf(w, a.w, s.w);
    }
    if (q > 0) s_part[(q - 1) * CPB + (t & (CPB - 1))] = s;
    __syncthreads();

    float v1 = 0.f;
    if (q == 0) {
        const int c = t;                                 // t < 256 here
        const float4 p1 = s_part[c];
        const float4 p2 = s_part[CPB + c];
        const float4 p3 = s_part[2 * CPB + c];
        const float sx = s.x + p1.x + p2.x + p3.x;
        const float sy = s.y + p1.y + p2.y + p3.y;
        const float sz = s.z + p1.z + p2.z + p3.z;
        const float sw = s.w + p1.w + p2.w + p3.w;
        v1 = sx*sx + sy*sy + sz*sz + sw*sw;
    }
    float v2 = my_diag;                 // nonzero only on lane0 of each warp

    #pragma unroll
    for (int o = 16; o; o >>= 1) {
        v1 += __shfl_xor_sync(0xffffffffu, v1, o);
        v2 += __shfl_xor_sync(0xffffffffu, v2, o);
    }
    if (lane == 0) { w1[warp] = v1; w2[warp] = v2; }
    __syncthreads();

    __shared__ bool s_last;
    if (t == 0) {
        float t1 = 0.f, t2 = 0.f;
        #pragma unroll
        for (int i = 0; i < NT / 32; i++) { t1 += w1[i]; t2 += w2[i]; }
        g_part[bid] = (double)t1 - (double)t2;
        __threadfence();
        unsigned int old = atomicAdd(&g_done, 1u);
        s_last = ((old & (GRID - 1)) == (GRID - 1));
    }
    __syncthreads();
    if (!s_last) return;

    // ---------------- Finisher: combine 256 partials in double --------------
    __threadfence();
    __shared__ double sd[GRID];
    if (t < GRID) sd[t] = g_part[t];
    __syncthreads();
    #pragma unroll
    for (int o = GRID / 2; o; o >>= 1) {
        if (t < o) sd[t] += sd[t + o];
        __syncthreads();
    }
    if (t == 0) out[0] = (float)(sd[0] / (double)BB);
}

extern "C" void kernel_launch(void* const* d_in, const int* in_sizes, int n_in,
                              void* d_out, int out_size) {
    (void)in_sizes; (void)n_in; (void)out_size;
    const float* x = (const float*)d_in[0];
    float* out = (float*)d_out;
    fused_loss<<<GRID, NT>>>(x, out);
}